// round 1
// baseline (speedup 1.0000x reference)
#include <cuda_runtime.h>

// Demosaic (Malvar-He-Cutler), 16x1x1024x1024 f32 -> 16x3x1024x1024 f32.
// One thread computes one 2x2 bayer quad. Shared-memory tile with 2-halo,
// edge replication via index clamping.

#define HH 1024
#define WW 1024
#define TW 64   // tile width (pixels)
#define TH 16   // tile height (pixels)
#define SW 68   // TW + 4
#define SH 20   // TH + 4

__device__ __forceinline__ void compute_pixel(
    float c, float sh1, float sh2, float sv1, float sv2, float sdiag,
    int ei, int ej, float& R, float& G, float& B)
{
    // eff parity (ei,ej) selects which feature feeds each output channel:
    // (0,0): R=x,  G=K0, B=K1
    // (0,1): R=K2, G=x,  B=K3
    // (1,0): R=K3, G=x,  B=K2
    // (1,1): R=K1, G=K0, B=x
    const float k0 = 0.0625f * (8.0f * c + 4.0f * (sh1 + sv1) - 2.0f * (sh2 + sv2));
    const float k1 = 0.0625f * (12.0f * c + 4.0f * sdiag - 3.0f * (sh2 + sv2));
    const float k2 = 0.0625f * (10.0f * c + 8.0f * sh1 + sv2 - 2.0f * sh2 - 2.0f * sdiag);
    const float k3 = 0.0625f * (10.0f * c + 8.0f * sv1 + sh2 - 2.0f * sv2 - 2.0f * sdiag);
    if (ei == 0) {
        if (ej == 0) { R = c;  G = k0; B = k1; }
        else         { R = k2; G = c;  B = k3; }
    } else {
        if (ej == 0) { R = k3; G = c;  B = k2; }
        else         { R = k1; G = k0; B = c;  }
    }
}

__global__ __launch_bounds__(256) void demosaic_kernel(
    const float* __restrict__ x,
    const int* __restrict__ bp,
    float* __restrict__ out)
{
    __shared__ __align__(16) float sm[SH * SW];

    const int n    = blockIdx.z;
    const int row0 = blockIdx.y * TH;
    const int col0 = blockIdx.x * TW;
    const float* xin = x + (size_t)n * (HH * WW);

    // ---- fill shared tile (rows row0-2 .. row0+TH+1, cols col0-2 .. col0+TW+1), clamped
    const int tid = threadIdx.y * 32 + threadIdx.x;
    #pragma unroll
    for (int idx = tid; idx < SH * SW; idx += 256) {
        int r = idx / SW;
        int c = idx - r * SW;
        int gr = min(max(row0 + r - 2, 0), HH - 1);
        int gc = min(max(col0 + c - 2, 0), WW - 1);
        sm[idx] = __ldg(&xin[gr * WW + gc]);
    }
    __syncthreads();

    // bayer pattern -> parity flips (uniform across grid)
    const int p0 = bp[0], p1 = bp[1];
    const int di = (p0 == 2) || (p0 == 1 && p1 == 2);
    const int dj = (p0 == 2) || (p0 == 1 && p1 == 0);

    const int lx = 2 * threadIdx.x;   // local pixel col of quad (even)
    const int ly = 2 * threadIdx.y;   // local pixel row of quad (even)

    // ---- load 6x6 register patch: rows ly..ly+5, cols lx..lx+5 of sm
    float v[6][6];
    #pragma unroll
    for (int i = 0; i < 6; i++) {
        const float2* p = (const float2*)&sm[(ly + i) * SW + lx];
        float2 a = p[0], b = p[1], c2 = p[2];
        v[i][0] = a.x;  v[i][1] = a.y;
        v[i][2] = b.x;  v[i][3] = b.y;
        v[i][4] = c2.x; v[i][5] = c2.y;
    }

    float R[2][2], G[2][2], B[2][2];

    #define PIX(I, J) do {                                                   \
        float c    = v[I][J];                                                \
        float sh1  = v[I][(J)-1] + v[I][(J)+1];                              \
        float sh2  = v[I][(J)-2] + v[I][(J)+2];                              \
        float sv1  = v[(I)-1][J] + v[(I)+1][J];                              \
        float sv2  = v[(I)-2][J] + v[(I)+2][J];                              \
        float sdg  = (v[(I)-1][(J)-1] + v[(I)-1][(J)+1])                     \
                   + (v[(I)+1][(J)-1] + v[(I)+1][(J)+1]);                    \
        compute_pixel(c, sh1, sh2, sv1, sv2, sdg,                            \
                      ((I) & 1) ^ di, ((J) & 1) ^ dj,                        \
                      R[(I)-2][(J)-2], G[(I)-2][(J)-2], B[(I)-2][(J)-2]);    \
    } while (0)

    PIX(2, 2);
    PIX(2, 3);
    PIX(3, 2);
    PIX(3, 3);
    #undef PIX

    // ---- coalesced float2 stores, 3 channels x 2 rows
    const int gr = row0 + ly;
    const int gc = col0 + lx;
    const size_t hw = (size_t)HH * WW;
    float* o = out + (size_t)n * 3 * hw + (size_t)gr * WW + gc;

    *(float2*)&o[0]           = make_float2(R[0][0], R[0][1]);
    *(float2*)&o[WW]          = make_float2(R[1][0], R[1][1]);
    *(float2*)&o[hw]          = make_float2(G[0][0], G[0][1]);
    *(float2*)&o[hw + WW]     = make_float2(G[1][0], G[1][1]);
    *(float2*)&o[2 * hw]      = make_float2(B[0][0], B[0][1]);
    *(float2*)&o[2 * hw + WW] = make_float2(B[1][0], B[1][1]);
}

extern "C" void kernel_launch(void* const* d_in, const int* in_sizes, int n_in,
                              void* d_out, int out_size)
{
    const float* x  = (const float*)d_in[0];
    const int*   bp = (const int*)d_in[1];
    float*       out = (float*)d_out;

    const int n_img = in_sizes[0] / (HH * WW);   // 16

    dim3 block(32, 8, 1);                        // 256 threads -> 64x16 pixel tile
    dim3 grid(WW / TW, HH / TH, n_img);          // (16, 64, 16)
    demosaic_kernel<<<grid, block>>>(x, bp, out);
}

// round 2
// speedup vs baseline: 1.2290x; 1.2290x over previous
#include <cuda_runtime.h>

// Malvar-He-Cutler demosaic, 16x1x1024x1024 f32 -> 16x3x1024x1024 f32.
// Each thread computes a 4x2 pixel region (two 2x2 bayer quads side by side).
// Shared tile with 2-halo; parity-templated compute so each pixel evaluates
// only the 2 filter kernels it actually needs.

#define HH 1024
#define WW 1024
#define TW 128  // tile width (pixels)
#define TH 16   // tile height (pixels)
#define SW 136  // TW + 8 (smem col s <-> global col col0 - 4 + s; float4 aligned)
#define SH 20   // TH + 4
#define CHUNKS (SW / 4)  // 34 float4 chunks per smem row

template <int DI, int DJ>
__device__ __forceinline__ void compute_tile(const float (&v)[6][8],
                                             float4 (&R4)[2],
                                             float4 (&G4)[2],
                                             float4 (&B4)[2]) {
    #pragma unroll
    for (int a = 0; a < 2; a++) {
        float ro[4], go[4], bo[4];
        #pragma unroll
        for (int q = 0; q < 4; q++) {
            const int i0 = a + 2;
            const int jc = q + 2;
            const float c   = v[i0][jc];
            const float sh1 = v[i0][jc - 1] + v[i0][jc + 1];
            const float sh2 = v[i0][jc - 2] + v[i0][jc + 2];
            const float sv1 = v[i0 - 1][jc] + v[i0 + 1][jc];
            const float sv2 = v[i0 - 2][jc] + v[i0 + 2][jc];
            const float sdg = (v[i0 - 1][jc - 1] + v[i0 - 1][jc + 1]) +
                              (v[i0 + 1][jc - 1] + v[i0 + 1][jc + 1]);
            const int ei = (a ^ DI) & 1;
            const int ej = (q ^ DJ) & 1;
            if (ei == ej) {
                // pixel sits on a red/blue site: needs k0 (green) + k1 (opposite)
                const float u  = sh2 + sv2;
                const float k0 = fmaf(0.25f, sh1 + sv1, 0.5f * c) - 0.125f * u;
                const float k1 = fmaf(0.25f, sdg, 0.75f * c) - 0.1875f * u;
                go[q] = k0;
                if (ei == 0) { ro[q] = c;  bo[q] = k1; }
                else         { ro[q] = k1; bo[q] = c;  }
            } else {
                // green site: needs k2 (horizontal) + k3 (vertical)
                const float k2 = fmaf(0.5f, sh1, 0.625f * c) +
                                 fmaf(0.0625f, sv2, -0.125f * sh2) - 0.125f * sdg;
                const float k3 = fmaf(0.5f, sv1, 0.625f * c) +
                                 fmaf(0.0625f, sh2, -0.125f * sv2) - 0.125f * sdg;
                go[q] = c;
                if (ei == 0) { ro[q] = k2; bo[q] = k3; }
                else         { ro[q] = k3; bo[q] = k2; }
            }
        }
        R4[a] = make_float4(ro[0], ro[1], ro[2], ro[3]);
        G4[a] = make_float4(go[0], go[1], go[2], go[3]);
        B4[a] = make_float4(bo[0], bo[1], bo[2], bo[3]);
    }
}

__global__ __launch_bounds__(256) void demosaic_kernel(
    const float* __restrict__ x,
    const int* __restrict__ bp,
    float* __restrict__ out)
{
    __shared__ __align__(16) float sm[SH * SW];

    const int n    = blockIdx.z;
    const int row0 = blockIdx.y * TH;
    const int col0 = blockIdx.x * TW;
    const float* xin = x + (size_t)n * (HH * WW);

    // ---- fill shared tile with float4 chunks; row clamp always, col clamp rare
    const int tid = threadIdx.y * 32 + threadIdx.x;
    #pragma unroll
    for (int idx = tid; idx < SH * CHUNKS; idx += 256) {
        const int r = idx / CHUNKS;
        const int c = idx - r * CHUNKS;
        const int gr = min(max(row0 + r - 2, 0), HH - 1);
        const int g0 = col0 - 4 + 4 * c;
        const float* rowp = xin + (size_t)gr * WW;
        float4 val;
        if (g0 >= 0 && g0 + 3 < WW) {
            val = *(const float4*)&rowp[g0];
        } else {
            val.x = rowp[min(max(g0 + 0, 0), WW - 1)];
            val.y = rowp[min(max(g0 + 1, 0), WW - 1)];
            val.z = rowp[min(max(g0 + 2, 0), WW - 1)];
            val.w = rowp[min(max(g0 + 3, 0), WW - 1)];
        }
        *(float4*)&sm[r * SW + 4 * c] = val;
    }
    __syncthreads();

    // bayer pattern -> parity flips (uniform across grid)
    const int p0 = bp[0], p1 = bp[1];
    const int di = (p0 == 2) || (p0 == 1 && p1 == 2);
    const int dj = (p0 == 2) || (p0 == 1 && p1 == 0);

    const int lx = 4 * threadIdx.x;   // pixel col of 4-wide strip (mult of 4)
    const int ly = 2 * threadIdx.y;   // pixel row of 2-high strip (even)

    // ---- register patch: smem rows ly..ly+5, smem cols lx+2..lx+9 (float2 loads)
    float v[6][8];
    #pragma unroll
    for (int i = 0; i < 6; i++) {
        const float2* p = (const float2*)&sm[(ly + i) * SW + lx + 2];
        float2 a = p[0], b = p[1], c2 = p[2], d2 = p[3];
        v[i][0] = a.x;  v[i][1] = a.y;
        v[i][2] = b.x;  v[i][3] = b.y;
        v[i][4] = c2.x; v[i][5] = c2.y;
        v[i][6] = d2.x; v[i][7] = d2.y;
    }

    float4 R4[2], G4[2], B4[2];
    if (di == 0) {
        if (dj == 0) compute_tile<0, 0>(v, R4, G4, B4);
        else         compute_tile<0, 1>(v, R4, G4, B4);
    } else {
        if (dj == 0) compute_tile<1, 0>(v, R4, G4, B4);
        else         compute_tile<1, 1>(v, R4, G4, B4);
    }

    // ---- float4 stores: 3 channels x 2 rows
    const int gr = row0 + ly;
    const int gc = col0 + lx;
    const size_t hw = (size_t)HH * WW;
    float* o = out + (size_t)n * 3 * hw + (size_t)gr * WW + gc;

    *(float4*)&o[0]           = R4[0];
    *(float4*)&o[WW]          = R4[1];
    *(float4*)&o[hw]          = G4[0];
    *(float4*)&o[hw + WW]     = G4[1];
    *(float4*)&o[2 * hw]      = B4[0];
    *(float4*)&o[2 * hw + WW] = B4[1];
}

extern "C" void kernel_launch(void* const* d_in, const int* in_sizes, int n_in,
                              void* d_out, int out_size)
{
    const float* x   = (const float*)d_in[0];
    const int*   bp  = (const int*)d_in[1];
    float*       out = (float*)d_out;

    const int n_img = in_sizes[0] / (HH * WW);   // 16

    dim3 block(32, 8, 1);                        // 256 threads -> 128x16 pixel tile
    dim3 grid(WW / TW, HH / TH, n_img);          // (8, 64, 16)
    demosaic_kernel<<<grid, block>>>(x, bp, out);
}

// round 3
// speedup vs baseline: 1.3798x; 1.1228x over previous
#include <cuda_runtime.h>

// Malvar-He-Cutler demosaic, 16x1x1024x1024 f32 -> 16x3x1024x1024 f32.
// 128-thread blocks, 64x16 tile, cp.async fill, 4x2 px per thread,
// parity-templated compute (only the 2 needed filter kernels per pixel).

#define HH 1024
#define WW 1024
#define TW 64   // tile width (pixels)
#define TH 16   // tile height (pixels)
#define SW 72   // TW + 8 (smem col s <-> global col col0 - 4 + s)
#define SH 20   // TH + 4
#define CHUNKS (SW / 4)  // 18 float4 chunks per smem row

template <int DI, int DJ>
__device__ __forceinline__ void compute_tile(const float (&v)[6][8],
                                             float4 (&R4)[2],
                                             float4 (&G4)[2],
                                             float4 (&B4)[2]) {
    #pragma unroll
    for (int a = 0; a < 2; a++) {
        float ro[4], go[4], bo[4];
        #pragma unroll
        for (int q = 0; q < 4; q++) {
            const int i0 = a + 2;
            const int jc = q + 2;
            const float c   = v[i0][jc];
            const float sh1 = v[i0][jc - 1] + v[i0][jc + 1];
            const float sh2 = v[i0][jc - 2] + v[i0][jc + 2];
            const float sv1 = v[i0 - 1][jc] + v[i0 + 1][jc];
            const float sv2 = v[i0 - 2][jc] + v[i0 + 2][jc];
            const float sdg = (v[i0 - 1][jc - 1] + v[i0 - 1][jc + 1]) +
                              (v[i0 + 1][jc - 1] + v[i0 + 1][jc + 1]);
            const int ei = (a ^ DI) & 1;
            const int ej = (q ^ DJ) & 1;
            if (ei == ej) {
                // red/blue site: needs k0 (green) + k1 (opposite channel)
                const float u  = sh2 + sv2;
                const float k0 = fmaf(0.25f, sh1 + sv1, 0.5f * c) - 0.125f * u;
                const float k1 = fmaf(0.25f, sdg, 0.75f * c) - 0.1875f * u;
                go[q] = k0;
                if (ei == 0) { ro[q] = c;  bo[q] = k1; }
                else         { ro[q] = k1; bo[q] = c;  }
            } else {
                // green site: needs k2 (horizontal) + k3 (vertical)
                const float k2 = fmaf(0.5f, sh1, 0.625f * c) +
                                 fmaf(0.0625f, sv2, -0.125f * sh2) - 0.125f * sdg;
                const float k3 = fmaf(0.5f, sv1, 0.625f * c) +
                                 fmaf(0.0625f, sh2, -0.125f * sv2) - 0.125f * sdg;
                go[q] = c;
                if (ei == 0) { ro[q] = k2; bo[q] = k3; }
                else         { ro[q] = k3; bo[q] = k2; }
            }
        }
        R4[a] = make_float4(ro[0], ro[1], ro[2], ro[3]);
        G4[a] = make_float4(go[0], go[1], go[2], go[3]);
        B4[a] = make_float4(bo[0], bo[1], bo[2], bo[3]);
    }
}

__global__ __launch_bounds__(128) void demosaic_kernel(
    const float* __restrict__ x,
    const int* __restrict__ bp,
    float* __restrict__ out)
{
    __shared__ __align__(16) float sm[SH * SW];

    const int n    = blockIdx.z;
    const int row0 = blockIdx.y * TH;
    const int col0 = blockIdx.x * TW;
    const float* xin = x + (size_t)n * (HH * WW);

    // ---- async fill of shared tile (rows clamped; col clamp only on edge tiles)
    const int tid = threadIdx.y * 16 + threadIdx.x;
    #pragma unroll
    for (int idx = tid; idx < SH * CHUNKS; idx += 128) {
        const int r = idx / CHUNKS;
        const int c = idx - r * CHUNKS;
        const int gr = min(max(row0 + r - 2, 0), HH - 1);
        const int g0 = col0 - 4 + 4 * c;
        const float* rowp = xin + (size_t)gr * WW;
        float* sp = &sm[r * SW + 4 * c];
        if (g0 >= 0 && g0 + 3 < WW) {
            unsigned saddr = (unsigned)__cvta_generic_to_shared(sp);
            asm volatile("cp.async.cg.shared.global [%0], [%1], 16;\n"
                         :: "r"(saddr), "l"(rowp + g0) : "memory");
        } else {
            sp[0] = rowp[min(max(g0 + 0, 0), WW - 1)];
            sp[1] = rowp[min(max(g0 + 1, 0), WW - 1)];
            sp[2] = rowp[min(max(g0 + 2, 0), WW - 1)];
            sp[3] = rowp[min(max(g0 + 3, 0), WW - 1)];
        }
    }
    asm volatile("cp.async.commit_group;\n" ::: "memory");

    // bayer pattern -> parity flips (uniform across grid)
    const int p0 = bp[0], p1 = bp[1];
    const int di = (p0 == 2) || (p0 == 1 && p1 == 2);
    const int dj = (p0 == 2) || (p0 == 1 && p1 == 0);

    asm volatile("cp.async.wait_group 0;\n" ::: "memory");
    __syncthreads();

    const int lx = 4 * threadIdx.x;   // pixel col of 4-wide strip
    const int ly = 2 * threadIdx.y;   // pixel row of 2-high strip

    // ---- register patch: smem rows ly..ly+5, smem cols lx+2..lx+9 (float2 loads)
    float v[6][8];
    #pragma unroll
    for (int i = 0; i < 6; i++) {
        const float2* p = (const float2*)&sm[(ly + i) * SW + lx + 2];
        float2 a = p[0], b = p[1], c2 = p[2], d2 = p[3];
        v[i][0] = a.x;  v[i][1] = a.y;
        v[i][2] = b.x;  v[i][3] = b.y;
        v[i][4] = c2.x; v[i][5] = c2.y;
        v[i][6] = d2.x; v[i][7] = d2.y;
    }

    float4 R4[2], G4[2], B4[2];
    if (di == 0) {
        if (dj == 0) compute_tile<0, 0>(v, R4, G4, B4);
        else         compute_tile<0, 1>(v, R4, G4, B4);
    } else {
        if (dj == 0) compute_tile<1, 0>(v, R4, G4, B4);
        else         compute_tile<1, 1>(v, R4, G4, B4);
    }

    // ---- float4 stores: 3 channels x 2 rows
    const int gr = row0 + ly;
    const int gc = col0 + lx;
    const size_t hw = (size_t)HH * WW;
    float* o = out + (size_t)n * 3 * hw + (size_t)gr * WW + gc;

    *(float4*)&o[0]           = R4[0];
    *(float4*)&o[WW]          = R4[1];
    *(float4*)&o[hw]          = G4[0];
    *(float4*)&o[hw + WW]     = G4[1];
    *(float4*)&o[2 * hw]      = B4[0];
    *(float4*)&o[2 * hw + WW] = B4[1];
}

extern "C" void kernel_launch(void* const* d_in, const int* in_sizes, int n_in,
                              void* d_out, int out_size)
{
    const float* x   = (const float*)d_in[0];
    const int*   bp  = (const int*)d_in[1];
    float*       out = (float*)d_out;

    const int n_img = in_sizes[0] / (HH * WW);   // 16

    dim3 block(16, 8, 1);                        // 128 threads -> 64x16 pixel tile
    dim3 grid(WW / TW, HH / TH, n_img);          // (16, 64, 16)
    demosaic_kernel<<<grid, block>>>(x, bp, out);
}

// round 4
// speedup vs baseline: 1.4513x; 1.0518x over previous
#include <cuda_runtime.h>

// Malvar-He-Cutler demosaic, 16x1x1024x1024 f32 -> 16x3x1024x1024 f32.
// 128-thread blocks. Each block owns a 64-wide x 64-tall strip, processed as
// 4 subtiles (64x16) with a double-buffered cp.async pipeline so fill latency
// of subtile s+1 is hidden behind compute of subtile s.

#define HH 1024
#define WW 1024
#define TW 64   // subtile width (pixels)
#define TH 16   // subtile height (pixels)
#define NSUB 4  // subtiles per block (vertical)
#define SW 72   // TW + 8
#define SH 20   // TH + 4
#define CHUNKS (SW / 4)  // 18 float4 chunks per smem row

__device__ __forceinline__ void fill_tile(float* __restrict__ sm,
                                          const float* __restrict__ xin,
                                          int row0, int col0, int tid)
{
    for (int idx = tid; idx < SH * CHUNKS; idx += 128) {
        const int r = idx / CHUNKS;
        const int c = idx - r * CHUNKS;
        const int gr = min(max(row0 + r - 2, 0), HH - 1);
        const int g0 = col0 - 4 + 4 * c;
        const float* rowp = xin + (size_t)gr * WW;
        float* sp = &sm[r * SW + 4 * c];
        if (g0 >= 0 && g0 + 3 < WW) {
            unsigned saddr = (unsigned)__cvta_generic_to_shared(sp);
            asm volatile("cp.async.cg.shared.global [%0], [%1], 16;\n"
                         :: "r"(saddr), "l"(rowp + g0) : "memory");
        } else {
            sp[0] = rowp[min(max(g0 + 0, 0), WW - 1)];
            sp[1] = rowp[min(max(g0 + 1, 0), WW - 1)];
            sp[2] = rowp[min(max(g0 + 2, 0), WW - 1)];
            sp[3] = rowp[min(max(g0 + 3, 0), WW - 1)];
        }
    }
    asm volatile("cp.async.commit_group;\n" ::: "memory");
}

template <int DI, int DJ>
__device__ __forceinline__ void compute_tile(const float (&v)[6][8],
                                             float4 (&R4)[2],
                                             float4 (&G4)[2],
                                             float4 (&B4)[2]) {
    #pragma unroll
    for (int a = 0; a < 2; a++) {
        float ro[4], go[4], bo[4];
        #pragma unroll
        for (int q = 0; q < 4; q++) {
            const int i0 = a + 2;
            const int jc = q + 2;
            const float c   = v[i0][jc];
            const float sh1 = v[i0][jc - 1] + v[i0][jc + 1];
            const float sh2 = v[i0][jc - 2] + v[i0][jc + 2];
            const float sv1 = v[i0 - 1][jc] + v[i0 + 1][jc];
            const float sv2 = v[i0 - 2][jc] + v[i0 + 2][jc];
            const float sdg = (v[i0 - 1][jc - 1] + v[i0 - 1][jc + 1]) +
                              (v[i0 + 1][jc - 1] + v[i0 + 1][jc + 1]);
            const int ei = (a ^ DI) & 1;
            const int ej = (q ^ DJ) & 1;
            if (ei == ej) {
                const float u  = sh2 + sv2;
                const float k0 = fmaf(0.25f, sh1 + sv1, 0.5f * c) - 0.125f * u;
                const float k1 = fmaf(0.25f, sdg, 0.75f * c) - 0.1875f * u;
                go[q] = k0;
                if (ei == 0) { ro[q] = c;  bo[q] = k1; }
                else         { ro[q] = k1; bo[q] = c;  }
            } else {
                const float k2 = fmaf(0.5f, sh1, 0.625f * c) +
                                 fmaf(0.0625f, sv2, -0.125f * sh2) - 0.125f * sdg;
                const float k3 = fmaf(0.5f, sv1, 0.625f * c) +
                                 fmaf(0.0625f, sh2, -0.125f * sv2) - 0.125f * sdg;
                go[q] = c;
                if (ei == 0) { ro[q] = k2; bo[q] = k3; }
                else         { ro[q] = k3; bo[q] = k2; }
            }
        }
        R4[a] = make_float4(ro[0], ro[1], ro[2], ro[3]);
        G4[a] = make_float4(go[0], go[1], go[2], go[3]);
        B4[a] = make_float4(bo[0], bo[1], bo[2], bo[3]);
    }
}

__global__ __launch_bounds__(128) void demosaic_kernel(
    const float* __restrict__ x,
    const int* __restrict__ bp,
    float* __restrict__ out)
{
    __shared__ __align__(16) float sm[2][SH * SW];

    const int n    = blockIdx.z;
    const int col0 = blockIdx.x * TW;
    const int yrow = blockIdx.y * (TH * NSUB);
    const float* xin = x + (size_t)n * (HH * WW);
    const int tid = threadIdx.y * 16 + threadIdx.x;

    // prologue: prefetch subtile 0
    fill_tile(sm[0], xin, yrow, col0, tid);

    // bayer pattern -> parity flips (uniform across grid)
    const int p0 = bp[0], p1 = bp[1];
    const int di = (p0 == 2) || (p0 == 1 && p1 == 2);
    const int dj = (p0 == 2) || (p0 == 1 && p1 == 0);

    const int lx = 4 * threadIdx.x;
    const int ly = 2 * threadIdx.y;
    const size_t hw = (size_t)HH * WW;
    float* obase = out + (size_t)n * 3 * hw + col0 + lx;

    #pragma unroll
    for (int s = 0; s < NSUB; s++) {
        const float* buf = sm[s & 1];
        if (s + 1 < NSUB) {
            fill_tile(sm[(s + 1) & 1], xin, yrow + (s + 1) * TH, col0, tid);
            asm volatile("cp.async.wait_group 1;\n" ::: "memory");
        } else {
            asm volatile("cp.async.wait_group 0;\n" ::: "memory");
        }
        __syncthreads();

        // register patch: smem rows ly..ly+5, cols lx+2..lx+9
        float v[6][8];
        #pragma unroll
        for (int i = 0; i < 6; i++) {
            const float2* p = (const float2*)&buf[(ly + i) * SW + lx + 2];
            float2 a = p[0], b = p[1], c2 = p[2], d2 = p[3];
            v[i][0] = a.x;  v[i][1] = a.y;
            v[i][2] = b.x;  v[i][3] = b.y;
            v[i][4] = c2.x; v[i][5] = c2.y;
            v[i][6] = d2.x; v[i][7] = d2.y;
        }

        float4 R4[2], G4[2], B4[2];
        if (di == 0) {
            if (dj == 0) compute_tile<0, 0>(v, R4, G4, B4);
            else         compute_tile<0, 1>(v, R4, G4, B4);
        } else {
            if (dj == 0) compute_tile<1, 0>(v, R4, G4, B4);
            else         compute_tile<1, 1>(v, R4, G4, B4);
        }

        // streaming float4 stores: 3 channels x 2 rows
        float* o = obase + (size_t)(yrow + s * TH + ly) * WW;
        __stcs((float4*)&o[0],           R4[0]);
        __stcs((float4*)&o[WW],          R4[1]);
        __stcs((float4*)&o[hw],          G4[0]);
        __stcs((float4*)&o[hw + WW],     G4[1]);
        __stcs((float4*)&o[2 * hw],      B4[0]);
        __stcs((float4*)&o[2 * hw + WW], B4[1]);

        __syncthreads();   // buf may be refilled at s+2
    }
}

extern "C" void kernel_launch(void* const* d_in, const int* in_sizes, int n_in,
                              void* d_out, int out_size)
{
    const float* x   = (const float*)d_in[0];
    const int*   bp  = (const int*)d_in[1];
    float*       out = (float*)d_out;

    const int n_img = in_sizes[0] / (HH * WW);   // 16

    dim3 block(16, 8, 1);                          // 128 threads
    dim3 grid(WW / TW, HH / (TH * NSUB), n_img);   // (16, 16, 16)
    demosaic_kernel<<<grid, block>>>(x, bp, out);
}

// round 5
// speedup vs baseline: 1.5454x; 1.0649x over previous
#include <cuda_runtime.h>

// Malvar-He-Cutler demosaic, 16x1x1024x1024 f32 -> 16x3x1024x1024 f32.
// No shared memory: each thread computes a 4x2 pixel region reading its
// 8x6 input window directly via __ldg float2 (L1 serves the 6x halo reuse).
// No barriers anywhere -> warps fully independent, 24-deep load MLP/thread.

#define HH 1024
#define WW 1024

template <int DI, int DJ>
__device__ __forceinline__ void compute_tile(const float (&v)[6][8],
                                             float4 (&R4)[2],
                                             float4 (&G4)[2],
                                             float4 (&B4)[2]) {
    #pragma unroll
    for (int a = 0; a < 2; a++) {
        float ro[4], go[4], bo[4];
        #pragma unroll
        for (int q = 0; q < 4; q++) {
            const int i0 = a + 2;
            const int jc = q + 2;
            const float c   = v[i0][jc];
            const float sh1 = v[i0][jc - 1] + v[i0][jc + 1];
            const float sh2 = v[i0][jc - 2] + v[i0][jc + 2];
            const float sv1 = v[i0 - 1][jc] + v[i0 + 1][jc];
            const float sv2 = v[i0 - 2][jc] + v[i0 + 2][jc];
            const float sdg = (v[i0 - 1][jc - 1] + v[i0 - 1][jc + 1]) +
                              (v[i0 + 1][jc - 1] + v[i0 + 1][jc + 1]);
            const int ei = (a ^ DI) & 1;
            const int ej = (q ^ DJ) & 1;
            if (ei == ej) {
                // red/blue site: needs k0 (green) + k1 (opposite channel)
                const float u  = sh2 + sv2;
                const float k0 = fmaf(0.25f, sh1 + sv1, 0.5f * c) - 0.125f * u;
                const float k1 = fmaf(0.25f, sdg, 0.75f * c) - 0.1875f * u;
                go[q] = k0;
                if (ei == 0) { ro[q] = c;  bo[q] = k1; }
                else         { ro[q] = k1; bo[q] = c;  }
            } else {
                // green site: needs k2 (horizontal) + k3 (vertical)
                const float k2 = fmaf(0.5f, sh1, 0.625f * c) +
                                 fmaf(0.0625f, sv2, -0.125f * sh2) - 0.125f * sdg;
                const float k3 = fmaf(0.5f, sv1, 0.625f * c) +
                                 fmaf(0.0625f, sh2, -0.125f * sv2) - 0.125f * sdg;
                go[q] = c;
                if (ei == 0) { ro[q] = k2; bo[q] = k3; }
                else         { ro[q] = k3; bo[q] = k2; }
            }
        }
        R4[a] = make_float4(ro[0], ro[1], ro[2], ro[3]);
        G4[a] = make_float4(go[0], go[1], go[2], go[3]);
        B4[a] = make_float4(bo[0], bo[1], bo[2], bo[3]);
    }
}

__global__ __launch_bounds__(256) void demosaic_kernel(
    const float* __restrict__ x,
    const int* __restrict__ bp,
    float* __restrict__ out)
{
    const int n  = blockIdx.z;
    const int gx = blockIdx.x * 128 + 4 * threadIdx.x;  // leftmost output col
    const int gy = blockIdx.y * 16  + 2 * threadIdx.y;  // top output row
    const float* __restrict__ xin = x + (size_t)n * (HH * WW);

    // ---- load 8x6 input window straight from global (L1 serves halo reuse)
    float v[6][8];
    const bool fastcol = (gx >= 2) && (gx + 10 <= WW);
    #pragma unroll
    for (int i = 0; i < 6; i++) {
        const int r = min(max(gy + i - 2, 0), HH - 1);
        const float* rowp = xin + (size_t)r * WW;
        if (fastcol) {
            float2 a  = __ldg((const float2*)(rowp + gx - 2));
            float2 b  = __ldg((const float2*)(rowp + gx));
            float2 c2 = __ldg((const float2*)(rowp + gx + 2));
            float2 d2 = __ldg((const float2*)(rowp + gx + 4));
            v[i][0] = a.x;  v[i][1] = a.y;
            v[i][2] = b.x;  v[i][3] = b.y;
            v[i][4] = c2.x; v[i][5] = c2.y;
            v[i][6] = d2.x; v[i][7] = d2.y;
        } else {
            #pragma unroll
            for (int j = 0; j < 8; j++)
                v[i][j] = __ldg(rowp + min(max(gx - 2 + j, 0), WW - 1));
        }
    }

    // bayer pattern -> parity flips (uniform across grid)
    const int p0 = bp[0], p1 = bp[1];
    const int di = (p0 == 2) || (p0 == 1 && p1 == 2);
    const int dj = (p0 == 2) || (p0 == 1 && p1 == 0);

    float4 R4[2], G4[2], B4[2];
    if (di == 0) {
        if (dj == 0) compute_tile<0, 0>(v, R4, G4, B4);
        else         compute_tile<0, 1>(v, R4, G4, B4);
    } else {
        if (dj == 0) compute_tile<1, 0>(v, R4, G4, B4);
        else         compute_tile<1, 1>(v, R4, G4, B4);
    }

    // ---- streaming float4 stores: 3 channels x 2 rows
    const size_t hw = (size_t)HH * WW;
    float* o = out + (size_t)n * 3 * hw + (size_t)gy * WW + gx;

    __stcs((float4*)&o[0],           R4[0]);
    __stcs((float4*)&o[WW],          R4[1]);
    __stcs((float4*)&o[hw],          G4[0]);
    __stcs((float4*)&o[hw + WW],     G4[1]);
    __stcs((float4*)&o[2 * hw],      B4[0]);
    __stcs((float4*)&o[2 * hw + WW], B4[1]);
}

extern "C" void kernel_launch(void* const* d_in, const int* in_sizes, int n_in,
                              void* d_out, int out_size)
{
    const float* x   = (const float*)d_in[0];
    const int*   bp  = (const int*)d_in[1];
    float*       out = (float*)d_out;

    const int n_img = in_sizes[0] / (HH * WW);   // 16

    dim3 block(32, 8, 1);                        // 256 threads -> 128x16 pixel tile
    dim3 grid(WW / 128, HH / 16, n_img);         // (8, 64, 16)
    demosaic_kernel<<<grid, block>>>(x, bp, out);
}